// round 9
// baseline (speedup 1.0000x reference)
#include <cuda_runtime.h>

#define TT 4096
#define EE 64
#define HH 4096
#define TKK 8
#define NG  64            // GEMM-role blocks
#define NB  148           // total blocks = one per SM (all co-resident)
#define CHB 32768         // fill chunk bytes (== smem zero-buffer size)

// ---- scratch (device globals; no allocations allowed) ----
__device__ int   g_id[TT * TKK];    // top-8 expert ids per token
__device__ float g_pr[TT * TKK];    // router prob per selected expert
__device__ int   g_pos[TT * TKK];   // dispatch position within capacity
__device__ int   g_chunk;           // fill-chunk dispenser
__device__ int   g_gemm_done;       // finished GEMM blocks
__device__ int   g_sync1;           // fill-complete barrier
__device__ int   g_sync2;           // exit barrier (last resets counters)

__device__ __forceinline__ unsigned smem_u32(const void* p)
{
    unsigned a;
    asm("{ .reg .u64 t; cvta.to.shared.u64 t, %1; cvt.u32.u64 %0, t; }"
        : "=r"(a) : "l"(p));
    return a;
}

// ---- TMA bulk fill: warp leader streams 32KB zero chunks smem -> global ----
__device__ __forceinline__ void fill_tma(char* __restrict__ outb, long long nbytes,
                                         unsigned sbuf)
{
    if ((threadIdx.x & 31) == 0) {
        for (;;) {
            int c = atomicAdd(&g_chunk, 1);
            long long base = (long long)c * CHB;
            if (base >= nbytes) break;
            unsigned sz = (unsigned)((base + CHB <= nbytes) ? CHB : (nbytes - base));
            unsigned long long ga = (unsigned long long)(outb + base);
            asm volatile("cp.async.bulk.global.shared::cta.bulk_group [%0], [%1], %2;"
                         :: "l"(ga), "r"(sbuf), "r"(sz) : "memory");
            asm volatile("cp.async.bulk.commit_group;" ::: "memory");
            asm volatile("cp.async.bulk.wait_group.read 8;" ::: "memory");
        }
        asm volatile("cp.async.bulk.wait_group 0;" ::: "memory");
        asm volatile("fence.proxy.async;" ::: "memory");
    }
    __syncwarp();
}

// ============================================================================
// mainA: single persistent kernel, 148 blocks x 256 thr.
//   bid <  NG : GEMM 64tok x 64exp tile + softmax + top-8; last GEMM block
//               computes dispatch positions (hidden under fill); all join fill.
//   bid >= NG : TMA zero-fill from the start.
//   Epilogue  : grid sync -> cooperative scatter -> counter reset.
// ============================================================================
__global__ void __launch_bounds__(256, 1) mainA(const float* __restrict__ x,
                                                const float* __restrict__ w,
                                                float* __restrict__ out,
                                                long long outn, int C)
{
    // [0, 32K): GEMM Xs/Ws overlay, later the TMA zero buffer
    // [32K, 40K): tail of Ws during GEMM, later rank scratch
    __shared__ __align__(128) char sraw[40960];
    __shared__ int s_flag;

    float* Xs = (float*)sraw;                 // [token][k]  stride 66
    float* Ws = (float*)(sraw + 64 * 66 * 4); // [expert][k] stride 66

    const int bid = blockIdx.x, tid = threadIdx.x;
    const int wrp = tid >> 5, lane = tid & 31;
    long long nbytes = outn * 4;
    unsigned sbuf = smem_u32(sraw);

    if (bid < NG) {
        // ---------------- GEMM role ----------------
        float* P = Xs;                            // logits overlay
        const int t0   = bid * 64;
        const int half = tid >> 7;
        const int ht   = tid & 127;
        const int tx   = ht & 15;                 // experts tx*4..tx*4+3
        const int ty   = ht >> 4;                 // tokens  ty*8..ty*8+7

        unsigned long long A[16];
        #pragma unroll
        for (int i = 0; i < 16; i++) A[i] = 0ull;

        for (int h0 = 0; h0 < HH / 2; h0 += 32) {
            #pragma unroll
            for (int rr = 0; rr < 16; rr++) {
                int i = rr * 256 + tid;
                int t = i >> 6, r = i & 63;
                int gk = h0 + ((r >> 5) << 11) + (r & 31);
                Xs[t * 66 + r] = x[(long long)(t0 + t) * HH + gk];
                Ws[t * 66 + r] = w[(long long)t * HH + gk];
            }
            __syncthreads();

            unsigned long long c[16];
            #pragma unroll
            for (int i = 0; i < 16; i++) c[i] = 0ull;

            const float* xb = &Xs[(ty * 8) * 66 + half * 32];
            const float* wb = &Ws[(tx * 4) * 66 + half * 32];

            #pragma unroll 4
            for (int kk2 = 0; kk2 < 16; kk2++) {
                float2 xt[8], wt[4];
                #pragma unroll
                for (int j = 0; j < 8; j++) xt[j] = *(const float2*)&xb[j * 66 + kk2 * 2];
                #pragma unroll
                for (int j = 0; j < 4; j++) wt[j] = *(const float2*)&wb[j * 66 + kk2 * 2];

                #pragma unroll
                for (int s = 0; s < 2; s++) {
                    float w0 = s ? wt[0].y : wt[0].x;
                    float w1 = s ? wt[1].y : wt[1].x;
                    float w2 = s ? wt[2].y : wt[2].x;
                    float w3 = s ? wt[3].y : wt[3].x;
                    unsigned long long wp0, wp1;
                    asm("mov.b64 %0, {%1, %2};" : "=l"(wp0)
                        : "r"(__float_as_uint(w0)), "r"(__float_as_uint(w1)));
                    asm("mov.b64 %0, {%1, %2};" : "=l"(wp1)
                        : "r"(__float_as_uint(w2)), "r"(__float_as_uint(w3)));
                    #pragma unroll
                    for (int j = 0; j < 8; j++) {
                        float xv = s ? xt[j].y : xt[j].x;
                        unsigned long long xx;
                        asm("mov.b64 %0, {%1, %1};" : "=l"(xx) : "r"(__float_as_uint(xv)));
                        asm("fma.rn.f32x2 %0, %1, %2, %0;" : "+l"(c[j * 2])     : "l"(wp0), "l"(xx));
                        asm("fma.rn.f32x2 %0, %1, %2, %0;" : "+l"(c[j * 2 + 1]) : "l"(wp1), "l"(xx));
                    }
                }
            }
            #pragma unroll
            for (int i = 0; i < 16; i++)
                asm("add.rn.f32x2 %0, %1, %0;" : "+l"(A[i]) : "l"(c[i]));
            __syncthreads();
        }

        // ---- combine K-halves into logits ----
        if (half == 1) {
            #pragma unroll
            for (int j = 0; j < 8; j++)
                #pragma unroll
                for (int p = 0; p < 2; p++) {
                    unsigned lo, hi;
                    asm("mov.b64 {%0, %1}, %2;" : "=r"(lo), "=r"(hi) : "l"(A[j * 2 + p]));
                    P[(ty * 8 + j) * 66 + tx * 4 + 2 * p]     = __uint_as_float(lo);
                    P[(ty * 8 + j) * 66 + tx * 4 + 2 * p + 1] = __uint_as_float(hi);
                }
        }
        __syncthreads();
        if (half == 0) {
            #pragma unroll
            for (int j = 0; j < 8; j++)
                #pragma unroll
                for (int p = 0; p < 2; p++) {
                    unsigned lo, hi;
                    asm("mov.b64 {%0, %1}, %2;" : "=r"(lo), "=r"(hi) : "l"(A[j * 2 + p]));
                    int b = (ty * 8 + j) * 66 + tx * 4 + 2 * p;
                    P[b]     += __uint_as_float(lo);
                    P[b + 1] += __uint_as_float(hi);
                }
        }
        __syncthreads();

        // ---- softmax + iterative top-8 (8 warps x 8 tokens) ----
        for (int tt = 0; tt < 8; tt++) {
            int t = wrp * 8 + tt;
            float v0 = P[t * 66 + lane], v1 = P[t * 66 + lane + 32];

            float m = fmaxf(v0, v1);
            #pragma unroll
            for (int o = 16; o; o >>= 1) m = fmaxf(m, __shfl_xor_sync(0xffffffffu, m, o));

            float z = __expf(v0 - m) + __expf(v1 - m);
            #pragma unroll
            for (int o = 16; o; o >>= 1) z += __shfl_xor_sync(0xffffffffu, z, o);

            float s0 = v0, s1 = v1;
            int   wid_[TKK];
            float wex[TKK];
            float ssum = 0.f;

            #pragma unroll
            for (int k = 0; k < TKK; k++) {
                unsigned b0 = __float_as_uint(s0);
                b0 ^= (b0 & 0x80000000u) ? 0xFFFFFFFFu : 0x80000000u;
                unsigned b1 = __float_as_uint(s1);
                b1 ^= (b1 & 0x80000000u) ? 0xFFFFFFFFu : 0x80000000u;
                unsigned long long k0 = ((unsigned long long)b0 << 6) | (unsigned)(63 - lane);
                unsigned long long k1 = ((unsigned long long)b1 << 6) | (unsigned)(63 - (lane + 32));
                unsigned long long kb = (k0 > k1) ? k0 : k1;
                #pragma unroll
                for (int o = 16; o; o >>= 1) {
                    unsigned long long ok = __shfl_xor_sync(0xffffffffu, kb, o);
                    if (ok > kb) kb = ok;
                }
                int widx = 63 - (int)(kb & 63);
                float wv = P[t * 66 + widx];
                wid_[k] = widx;
                float ew = __expf(wv - m);
                wex[k] = ew;
                ssum += ew;
                if (widx < 32) { if (lane == widx)      s0 = __int_as_float(0xff800000); }
                else           { if (lane == widx - 32) s1 = __int_as_float(0xff800000); }
            }

            float gs    = ssum / z;
            float denom = fmaxf(gs, 1.1920929e-07f);
            if (lane == 0) {
                int tok = t0 + t;
                #pragma unroll
                for (int k = 0; k < TKK; k++) {
                    g_id[tok * TKK + k] = wid_[k];
                    g_pr[tok * TKK + k] = wex[k] / (z * denom);
                }
            }
        }

        // ---- zero the TMA source buffer [0, 32K) ----
        __syncthreads();
        {
            float4 zz = make_float4(0.f, 0.f, 0.f, 0.f);
            float4* b4 = (float4*)sraw;
            #pragma unroll
            for (int i = 0; i < CHB / 16 / 256; i++)
                b4[i * 256 + tid] = zz;
        }
        __syncthreads();
        __threadfence();
        if (tid == 0) s_flag = (atomicAdd(&g_gemm_done, 1) == NG - 1);
        __syncthreads();

        if (s_flag) {
            // ======== rank/position computation (hidden under fill) ========
            __threadfence();                      // acquire other blocks' g_id
            int* cnt = (int*)(sraw + CHB);        // [8][64]
            int* sb  = cnt + TKK * EE;            // [8][64] bases
            int* rc  = sb + TKK * EE;             // [8][64] running counts

            for (int i = tid; i < TKK * EE; i += 256) cnt[i] = 0;
            __syncthreads();
            for (int i = tid; i < TT * TKK; i += 256)
                atomicAdd(&cnt[(i & 7) * EE + g_id[i]], 1);
            __syncthreads();

            {   // warp wrp handles k = wrp
                int k = wrp;
                for (int e = lane; e < EE; e += 32) {
                    int b = 0;
                    for (int kp = 0; kp < k; kp++) b += cnt[kp * EE + e];
                    sb[k * EE + e] = b;
                    rc[k * EE + e] = 0;
                }
                __syncwarp();
                for (int t0r = 0; t0r < TT; t0r += 32) {
                    int t = t0r + lane;
                    int e = g_id[t * TKK + k];
                    unsigned peers = __match_any_sync(0xffffffffu, e);
                    int before = __popc(peers & ((1u << lane) - 1));
                    int rb = rc[k * EE + e];
                    __syncwarp();
                    if (before == 0) rc[k * EE + e] = rb + __popc(peers);
                    g_pos[t * TKK + k] = sb[k * EE + e] + rb + before;
                    __syncwarp();
                }
            }
            __syncthreads();
            __threadfence();                      // publish g_pos before sync1
        }

        asm volatile("fence.proxy.async.shared::cta;" ::: "memory");
        fill_tma((char*)out, nbytes, sbuf);       // join the fill
    } else {
        // ---------------- fill role ----------------
        {
            float4 zz = make_float4(0.f, 0.f, 0.f, 0.f);
            float4* b4 = (float4*)sraw;
            #pragma unroll
            for (int i = 0; i < CHB / 16 / 256; i++)
                b4[i * 256 + tid] = zz;
        }
        __syncthreads();
        asm volatile("fence.proxy.async.shared::cta;" ::: "memory");
        fill_tma((char*)out, nbytes, sbuf);
    }

    // ================= epilogue: grid sync -> scatter -> reset =============
    __threadfence();
    __syncthreads();
    if (tid == 0) {
        atomicAdd(&g_sync1, 1);
        while (*(volatile int*)&g_sync1 < NB) __nanosleep(128);
    }
    __syncthreads();
    __threadfence();

    {   // cooperative scatter: 32768 entries over 148*256 threads
        long long halfOff = (long long)TT * EE * C;
        for (int i = bid * 256 + tid; i < TT * TKK; i += NB * 256) {
            int t = i >> 3;
            int e = g_id[i];
            int p = g_pos[i];
            if (p < C) {
                long long idx = ((long long)t * EE + e) * C + p;
                out[idx]           = g_pr[i];
                out[halfOff + idx] = 1.0f;
            }
        }
    }

    __syncthreads();
    if (tid == 0) {
        if (atomicAdd(&g_sync2, 1) == NB - 1) {   // last block resets all
            g_chunk = 0; g_gemm_done = 0; g_sync1 = 0; g_sync2 = 0;
            __threadfence();
        }
    }
}

extern "C" void kernel_launch(void* const* d_in, const int* in_sizes, int n_in,
                              void* d_out, int out_size)
{
    const float* x = (const float*)d_in[0];   // hidden_states [1,4096,4096]
    const float* w = (const float*)d_in[1];   // wg_weight [64,4096]
    float* out = (float*)d_out;

    long long outn = (long long)out_size;
    int C = (int)(outn / (2LL * TT * EE));    // capacity from buffer size

    mainA<<<NB, 256>>>(x, w, out, outn, C);   // everything in one launch
}

// round 10
// speedup vs baseline: 1.0366x; 1.0366x over previous
#include <cuda_runtime.h>

#define TT 4096
#define EE 64
#define HH 4096
#define TKK 8
#define NG  64            // GEMM-role blocks (they join fill when done)
#define NB  148           // total blocks = one per SM
#define CHUNK 4096        // float4s per warp fill chunk (64KB)

// ---- scratch (device globals; no allocations allowed) ----
__device__ int   g_id[TT * TKK];    // top-8 expert ids per token
__device__ float g_pr[TT * TKK];    // router prob for each selected expert
__device__ int   g_chunk;           // fill-chunk dispenser (reset by kB2)

// ---- warp-level fill: grab 64KB chunks until exhausted ----
__device__ __forceinline__ void fill_warp(float4* __restrict__ o4, long long n4)
{
    const int lane = threadIdx.x & 31;
    const float4 z = make_float4(0.f, 0.f, 0.f, 0.f);
    for (;;) {
        int c = 0;
        if (lane == 0) c = atomicAdd(&g_chunk, 1);
        c = __shfl_sync(0xffffffffu, c, 0);
        long long base = (long long)c * CHUNK;
        if (base >= n4) return;
        if (base + CHUNK <= n4) {
            #pragma unroll 4
            for (int j = 0; j < CHUNK / 32; j++)
                __stcs(o4 + base + lane + j * 32, z);
        } else {
            for (long long i = base + lane; i < n4; i += 32)
                __stcs(o4 + i, z);
        }
    }
}

// ============================================================================
// mainA (identical to R6 best): 148 blocks x 256 thr.
//   bid <  NG : GEMM 64tok x 64exp tile (K-split2, 8tok x 4exp register tile,
//               f32x2 FMA) + softmax + top-8, THEN joins the fill.
//   bid >= NG : zero-fill role from the start (warp chunk dispenser).
// ============================================================================
__global__ void __launch_bounds__(256, 1) mainA(const float* __restrict__ x,
                                                const float* __restrict__ w,
                                                float* __restrict__ out,
                                                long long outn)
{
    const int bid = blockIdx.x, tid = threadIdx.x;
    long long n4 = outn >> 2;

    if (bid >= NG) {                      // ---------------- fill role
        fill_warp((float4*)out, n4);
        return;
    }

    // ---------------- GEMM role ----------------
    __shared__ __align__(16) float Xs[64 * 66];   // [token][k] stride 66
    __shared__ __align__(16) float Ws[64 * 66];   // [expert][k] stride 66
    float* P = Xs;                                // logits overlay

    const int t0   = bid * 64;
    const int half = tid >> 7;        // K-split half
    const int ht   = tid & 127;
    const int tx   = ht & 15;         // experts tx*4 .. tx*4+3
    const int ty   = ht >> 4;         // tokens  ty*8 .. ty*8+7

    unsigned long long A[16];
    #pragma unroll
    for (int i = 0; i < 16; i++) A[i] = 0ull;

    for (int h0 = 0; h0 < HH / 2; h0 += 32) {
        #pragma unroll
        for (int rr = 0; rr < 16; rr++) {
            int i = rr * 256 + tid;
            int t = i >> 6, r = i & 63;
            int gk = h0 + ((r >> 5) << 11) + (r & 31);
            Xs[t * 66 + r] = x[(long long)(t0 + t) * HH + gk];
            Ws[t * 66 + r] = w[(long long)t * HH + gk];
        }
        __syncthreads();

        unsigned long long c[16];
        #pragma unroll
        for (int i = 0; i < 16; i++) c[i] = 0ull;

        const float* xb = &Xs[(ty * 8) * 66 + half * 32];
        const float* wb = &Ws[(tx * 4) * 66 + half * 32];

        #pragma unroll 4
        for (int kk2 = 0; kk2 < 16; kk2++) {
            float2 xt[8], wt[4];
            #pragma unroll
            for (int j = 0; j < 8; j++) xt[j] = *(const float2*)&xb[j * 66 + kk2 * 2];
            #pragma unroll
            for (int j = 0; j < 4; j++) wt[j] = *(const float2*)&wb[j * 66 + kk2 * 2];

            #pragma unroll
            for (int s = 0; s < 2; s++) {
                float w0 = s ? wt[0].y : wt[0].x;
                float w1 = s ? wt[1].y : wt[1].x;
                float w2 = s ? wt[2].y : wt[2].x;
                float w3 = s ? wt[3].y : wt[3].x;
                unsigned long long wp0, wp1;
                asm("mov.b64 %0, {%1, %2};" : "=l"(wp0)
                    : "r"(__float_as_uint(w0)), "r"(__float_as_uint(w1)));
                asm("mov.b64 %0, {%1, %2};" : "=l"(wp1)
                    : "r"(__float_as_uint(w2)), "r"(__float_as_uint(w3)));
                #pragma unroll
                for (int j = 0; j < 8; j++) {
                    float xv = s ? xt[j].y : xt[j].x;
                    unsigned long long xx;
                    asm("mov.b64 %0, {%1, %1};" : "=l"(xx) : "r"(__float_as_uint(xv)));
                    asm("fma.rn.f32x2 %0, %1, %2, %0;" : "+l"(c[j * 2])     : "l"(wp0), "l"(xx));
                    asm("fma.rn.f32x2 %0, %1, %2, %0;" : "+l"(c[j * 2 + 1]) : "l"(wp1), "l"(xx));
                }
            }
        }
        #pragma unroll
        for (int i = 0; i < 16; i++)
            asm("add.rn.f32x2 %0, %1, %0;" : "+l"(A[i]) : "l"(c[i]));
        __syncthreads();
    }

    // ---- combine K-halves into logits P[t*66+e] ----
    if (half == 1) {
        #pragma unroll
        for (int j = 0; j < 8; j++)
            #pragma unroll
            for (int p = 0; p < 2; p++) {
                unsigned lo, hi;
                asm("mov.b64 {%0, %1}, %2;" : "=r"(lo), "=r"(hi) : "l"(A[j * 2 + p]));
                P[(ty * 8 + j) * 66 + tx * 4 + 2 * p]     = __uint_as_float(lo);
                P[(ty * 8 + j) * 66 + tx * 4 + 2 * p + 1] = __uint_as_float(hi);
            }
    }
    __syncthreads();
    if (half == 0) {
        #pragma unroll
        for (int j = 0; j < 8; j++)
            #pragma unroll
            for (int p = 0; p < 2; p++) {
                unsigned lo, hi;
                asm("mov.b64 {%0, %1}, %2;" : "=r"(lo), "=r"(hi) : "l"(A[j * 2 + p]));
                int b = (ty * 8 + j) * 66 + tx * 4 + 2 * p;
                P[b]     += __uint_as_float(lo);
                P[b + 1] += __uint_as_float(hi);
            }
    }
    __syncthreads();

    // ---- softmax + iterative top-8 (8 warps x 8 tokens) ----
    const int wrp = tid >> 5, lane = tid & 31;
    for (int tt = 0; tt < 8; tt++) {
        int t = wrp * 8 + tt;
        float v0 = P[t * 66 + lane], v1 = P[t * 66 + lane + 32];

        float m = fmaxf(v0, v1);
        #pragma unroll
        for (int o = 16; o; o >>= 1) m = fmaxf(m, __shfl_xor_sync(0xffffffffu, m, o));

        float z = __expf(v0 - m) + __expf(v1 - m);
        #pragma unroll
        for (int o = 16; o; o >>= 1) z += __shfl_xor_sync(0xffffffffu, z, o);

        float s0 = v0, s1 = v1;
        int   wid_[TKK];
        float wex[TKK];
        float ssum = 0.f;

        #pragma unroll
        for (int k = 0; k < TKK; k++) {
            unsigned b0 = __float_as_uint(s0);
            b0 ^= (b0 & 0x80000000u) ? 0xFFFFFFFFu : 0x80000000u;
            unsigned b1 = __float_as_uint(s1);
            b1 ^= (b1 & 0x80000000u) ? 0xFFFFFFFFu : 0x80000000u;
            unsigned long long k0 = ((unsigned long long)b0 << 6) | (unsigned)(63 - lane);
            unsigned long long k1 = ((unsigned long long)b1 << 6) | (unsigned)(63 - (lane + 32));
            unsigned long long kb = (k0 > k1) ? k0 : k1;
            #pragma unroll
            for (int o = 16; o; o >>= 1) {
                unsigned long long ok = __shfl_xor_sync(0xffffffffu, kb, o);
                if (ok > kb) kb = ok;
            }
            int widx = 63 - (int)(kb & 63);
            float wv = P[t * 66 + widx];
            wid_[k] = widx;
            float ew = __expf(wv - m);
            wex[k] = ew;
            ssum += ew;
            if (widx < 32) { if (lane == widx)      s0 = __int_as_float(0xff800000); }
            else           { if (lane == widx - 32) s1 = __int_as_float(0xff800000); }
        }

        float gs    = ssum / z;
        float denom = fmaxf(gs, 1.1920929e-07f);
        if (lane == 0) {
            int tok = t0 + t;
            #pragma unroll
            for (int k = 0; k < TKK; k++) {
                g_id[tok * TKK + k] = wid_[k];
                g_pr[tok * TKK + k] = wex[k] / (z * denom);
            }
        }
    }

    // ---- GEMM done: join the fill ----
    fill_warp((float4*)out, n4);
}

// ============================================================================
// kB2: parallel tail. 8 blocks (one per k), 256 thr.
//   1) count all (k',e) pairs (atomics, L2-hot)   ~4us
//   2) base[e] = sum_{k'<k} cnt[k'][e]
//   3) warp-parallel rank via __match_any_sync over tokens in order
//   4) scatter this k's 4096 (weight, mask) pairs
//   Also resets the fill dispenser for the next graph replay.
// ============================================================================
__global__ void __launch_bounds__(256) kB2(float* __restrict__ out, int C)
{
    const int k = blockIdx.x, tid = threadIdx.x;
    const int lane = tid & 31, wrp = tid >> 5;

    __shared__ int cnt[TKK * EE];
    __shared__ int sb[EE];            // base for this k
    __shared__ int rc[EE];            // running count within k
    __shared__ int spos[TT];          // positions for this k
    __shared__ int sid[TT];           // expert ids for this k

    if (k == 0 && tid == 0) g_chunk = 0;      // reset dispenser for next replay

    for (int i = tid; i < TKK * EE; i += 256) cnt[i] = 0;
    for (int i = tid; i < TT; i += 256) sid[i] = g_id[i * TKK + k];
    __syncthreads();

    for (int i = tid; i < TT * TKK; i += 256)
        atomicAdd(&cnt[(i & 7) * EE + g_id[i]], 1);
    __syncthreads();

    if (tid < EE) {
        int b = 0;
        for (int kp = 0; kp < k; kp++) b += cnt[kp * EE + tid];
        sb[tid] = b;
        rc[tid] = 0;
    }
    __syncthreads();

    if (wrp == 0) {                   // warp 0: ordered rank scan (match_any)
        for (int t0r = 0; t0r < TT; t0r += 32) {
            int t = t0r + lane;
            int e = sid[t];
            unsigned peers = __match_any_sync(0xffffffffu, e);
            int before = __popc(peers & ((1u << lane) - 1));
            int rb = rc[e];
            __syncwarp();
            if (before == 0) rc[e] = rb + __popc(peers);
            spos[t] = sb[e] + rb + before;
            __syncwarp();
        }
    }
    __syncthreads();

    {   // all 8 warps scatter this k's entries
        long long halfOff = (long long)TT * EE * C;
        for (int t = tid; t < TT; t += 256) {
            int e = sid[t];
            int p = spos[t];
            if (p < C) {
                long long idx = ((long long)t * EE + e) * C + p;
                out[idx]           = g_pr[t * TKK + k];
                out[halfOff + idx] = 1.0f;
            }
        }
    }
}

extern "C" void kernel_launch(void* const* d_in, const int* in_sizes, int n_in,
                              void* d_out, int out_size)
{
    const float* x = (const float*)d_in[0];   // hidden_states [1,4096,4096]
    const float* w = (const float*)d_in[1];   // wg_weight [64,4096]
    float* out = (float*)d_out;

    long long outn = (long long)out_size;
    int C = (int)(outn / (2LL * TT * EE));    // capacity from buffer size

    mainA<<<NB, 256>>>(x, w, out, outn);      // fill (all SMs) || GEMM+top8
    kB2<<<TKK, 256>>>(out, C);                // parallel ranks + scatter, reset
}